// round 8
// baseline (speedup 1.0000x reference)
#include <cuda_runtime.h>
#include <cuda_bf16.h>

// ---------------------------------------------------------------------------
// HGNN, 5-kernel pipeline v3: pass kernels use shared-memory hash tables
// (1 block/SM x 1024 thr) so per-edge probes hit the LDS pipe, not the LSU
// LDG port (which was the measured 1.82cyc/LDG bottleneck in R7).
// ---------------------------------------------------------------------------

#define NMAX     100000
#define MAX_S2   32
#define MAX_L2E  2048
#define MAX_S1   (MAX_L2E + MAX_S2 + 64)
#define H1TBL    4096
#define H1MASK   4095
#define RTBL     4096
#define RMASK    4095
#define RCAP     3500
#define MAX_L1E  32768
#define GRIDP    148
#define PTPB     1024

__device__ float g_deg[NMAX];                 // lazily zeroed at rtab_insert
__device__ int   g_h1pack[H1TBL];             // (slot<<17)|(node+1); 0 empty
__device__ int   g_rtab[RTBL];                // node+1; 0 empty
__device__ int   g_s2_node[MAX_S2];
__device__ float g_s2_val[MAX_S2];
__device__ int   g_s2_s1slot[MAX_S2];
__device__ int   g_l2_row[MAX_L2E];
__device__ int   g_l2_cslot[MAX_L2E];
__device__ int   g_l2_rslot[MAX_L2E];
__device__ float g_l2_w[MAX_L2E];
__device__ int   g_s1_node[MAX_S1];           // -1 = wasted slot
__device__ int   g_l1_row[MAX_L1E];
__device__ int   g_l1_cslot[MAX_L1E];
__device__ float g_l1_w[MAX_L1E];
__device__ float g_h1[MAX_S1 * 256];
__device__ float g_z[256];
__device__ float g_f1[512];
__device__ int   g_s2_count, g_l2e_count, g_l1e_count, g_s1_count, g_r_count, g_is32;
__device__ unsigned long long g_argmax_key;
__device__ int               g_marr[3];
__device__ volatile unsigned g_mph[3];        // monotonic mini phases

__device__ __forceinline__ unsigned hsh(int v) {
    return ((unsigned)v * 2654435761u) >> 13;
}

__device__ void rtab_insert(int node) {
    if (g_r_count >= RCAP) return;
    unsigned idx = hsh(node) & RMASK;
    for (int p = 0; p < RTBL; p++) {
        int cur = atomicCAS(&g_rtab[idx], 0, node + 1);
        if (cur == 0) { g_deg[node] = 0.0f; atomicAdd(&g_r_count, 1); return; }
        if (cur == node + 1) return;
        idx = (idx + 1) & RMASK;
    }
}

// Insert node into S1 hash; returns dense slot. Slot packed with node in one
// CAS word so readers always see complete pairs. Lost races burn a slot.
__device__ int h1_insert(int node) {
    unsigned idx = hsh(node) & H1MASK;
    int myslot = -1;
    for (int p = 0; p < H1TBL; p++) {
        int v = g_h1pack[idx];
        if (v != 0) {
            if ((v & 0x1FFFF) == node + 1) {
                if (myslot >= 0) g_s1_node[myslot] = -1;
                return v >> 17;
            }
        } else {
            if (myslot < 0) {
                myslot = atomicAdd(&g_s1_count, 1);
                if (myslot >= MAX_S1) return -1;
            }
            int cur = atomicCAS(&g_h1pack[idx], 0, (myslot << 17) | (node + 1));
            if (cur == 0) {
                g_s1_node[myslot] = node;
                rtab_insert(node);
                return myslot;
            }
            if ((cur & 0x1FFFF) == node + 1) {
                g_s1_node[myslot] = -1;
                return cur >> 17;
            }
        }
        idx = (idx + 1) & H1MASK;
    }
    return -1;
}

// ===========================================================================
// k0: dtype detect (warp ballot) + mask scan (S2 + argmax)
__global__ void k0_mask(const float* __restrict__ mask,
                        const long long* __restrict__ ei64, int n, int E) {
    __shared__ unsigned long long sk[256];
    int i = blockIdx.x * blockDim.x + threadIdx.x;
    int lim = E < 1024 ? E : 1024;
    if (i < lim) {
        long long v = ei64[i];
        bool bad = (v < 0 || v >= (long long)n);
        if (__any_sync(__activemask(), bad)) {
            if ((threadIdx.x & 31) == 0) g_is32 = 1;
        }
    }
    unsigned long long key = 0ull;
    if (i < n) {
        float m = mask[i];
        if (m != 0.0f) {
            int slot = atomicAdd(&g_s2_count, 1);
            if (slot < MAX_S2) {
                g_s2_node[slot] = i; g_s2_val[slot] = m;
                g_s2_s1slot[slot] = h1_insert(i);
            }
        }
        unsigned int b  = __float_as_uint(m);
        unsigned int ub = (b & 0x80000000u) ? ~b : (b | 0x80000000u);
        key = (((unsigned long long)ub) << 32) |
              (unsigned long long)(0xFFFFFFFFu - (unsigned)i);
    }
    sk[threadIdx.x] = key;
    __syncthreads();
    for (int o = 128; o > 0; o >>= 1) {
        if (threadIdx.x < o) {
            unsigned long long a = sk[threadIdx.x], b2 = sk[threadIdx.x + o];
            sk[threadIdx.x] = (a > b2) ? a : b2;
        }
        __syncthreads();
    }
    if (threadIdx.x == 0 && sk[0] != 0ull) atomicMax(&g_argmax_key, sk[0]);
}

// ===========================================================================
// k1: passA — edges into S2 (shared-broadcast compare); inline S1 hash build
__global__ __launch_bounds__(PTPB) void k1_passA(
        const long long* __restrict__ ei64, const float* __restrict__ ew, int E) {
    __shared__ int s2n[MAX_S2];
    __shared__ int ns2_s, is32_s;
    if (threadIdx.x == 0) { ns2_s = min(g_s2_count, MAX_S2); is32_s = g_is32; }
    __syncthreads();
    int ns2 = ns2_s, is32 = is32_s;
    if (threadIdx.x < ns2) s2n[threadIdx.x] = g_s2_node[threadIdx.x];
    __syncthreads();
    const int* ei32 = (const int*)ei64;
    int gsz  = gridDim.x * blockDim.x;
    int gtid = blockIdx.x * blockDim.x + threadIdx.x;
#define DO_A(cc, ee) do {                                                    \
        int _c = (cc); int _ms = -1;                                         \
        for (int _j = 0; _j < ns2; _j++) if (_c == s2n[_j]) _ms = _j;        \
        if (_ms >= 0) {                                                      \
            int _e = (ee);                                                   \
            int _r = is32 ? ei32[_e] : (int)ei64[_e];                        \
            int _sl = atomicAdd(&g_l2e_count, 1);                            \
            if (_sl < MAX_L2E) {                                             \
                g_l2_row[_sl] = _r; g_l2_cslot[_sl] = _ms;                   \
                g_l2_w[_sl] = ew[_e];                                        \
                g_l2_rslot[_sl] = h1_insert(_r);                             \
            }                                                                \
        }                                                                    \
    } while (0)
    if (is32 && ((E & 3) == 0)) {
        const int4* col4 = (const int4*)(ei32 + E);
        int nvec = E >> 2;
        for (int v = gtid; v < nvec; v += gsz) {
            int4 c4 = col4[v]; int e = v * 4;
            DO_A(c4.x, e); DO_A(c4.y, e + 1); DO_A(c4.z, e + 2); DO_A(c4.w, e + 3);
        }
    } else if (!is32 && ((E & 1) == 0)) {
        const longlong2* col2 = (const longlong2*)(ei64 + E);
        int nvec = E >> 1;
        for (int v = gtid; v < nvec; v += gsz) {
            longlong2 c2 = col2[v]; int e = v * 2;
            DO_A((int)c2.x, e); DO_A((int)c2.y, e + 1);
        }
    } else {
        for (int e = gtid; e < E; e += gsz)
            DO_A(is32 ? ei32[E + e] : (int)ei64[E + e], e);
    }
#undef DO_A
}

// ===========================================================================
// k2: passB — edges into S1 (probe SHARED copy of H1 hash); record L1 edges
__global__ __launch_bounds__(PTPB) void k2_passB(
        const long long* __restrict__ ei64, const float* __restrict__ ew, int E) {
    __shared__ int stab[H1TBL];                      // 16 KB
    {   // coalesced int4 copy: 4096 words = 1024 int4
        const int4* src = (const int4*)g_h1pack;
        int4* dst = (int4*)stab;
        for (int i = threadIdx.x; i < H1TBL / 4; i += PTPB) dst[i] = src[i];
    }
    __syncthreads();
    const int* ei32 = (const int*)ei64;
    int is32 = g_is32;
    int gsz  = gridDim.x * blockDim.x;
    int gtid = blockIdx.x * blockDim.x + threadIdx.x;
#define DO_B(cc, ee) do {                                                    \
        int _c = (cc);                                                       \
        unsigned _ix = hsh(_c) & H1MASK; int _sl = -1;                       \
        for (int _p = 0; _p < H1TBL; _p++) {                                 \
            int _v = stab[_ix];                                              \
            if (_v == 0) break;                                              \
            if ((_v & 0x1FFFF) == _c + 1) { _sl = _v >> 17; break; }         \
            _ix = (_ix + 1) & H1MASK;                                        \
        }                                                                    \
        if (_sl >= 0) {                                                      \
            int _e = (ee);                                                   \
            int _r = is32 ? ei32[_e] : (int)ei64[_e];                        \
            int _ps = atomicAdd(&g_l1e_count, 1);                            \
            if (_ps < MAX_L1E) {                                             \
                g_l1_row[_ps] = _r; g_l1_cslot[_ps] = _sl;                   \
                g_l1_w[_ps] = ew[_e];                                        \
                rtab_insert(_r);                                             \
            }                                                                \
        }                                                                    \
    } while (0)
    if (is32 && ((E & 3) == 0)) {
        const int4* col4 = (const int4*)(ei32 + E);
        int nvec = E >> 2;
        for (int v = gtid; v < nvec; v += gsz) {
            int4 c4 = col4[v]; int e = v * 4;
            DO_B(c4.x, e); DO_B(c4.y, e + 1); DO_B(c4.z, e + 2); DO_B(c4.w, e + 3);
        }
    } else if (!is32 && ((E & 1) == 0)) {
        const longlong2* col2 = (const longlong2*)(ei64 + E);
        int nvec = E >> 1;
        for (int v = gtid; v < nvec; v += gsz) {
            longlong2 c2 = col2[v]; int e = v * 2;
            DO_B((int)c2.x, e); DO_B((int)c2.y, e + 1);
        }
    } else {
        for (int e = gtid; e < E; e += gsz)
            DO_B(is32 ? ei32[E + e] : (int)ei64[E + e], e);
    }
#undef DO_B
}

// ===========================================================================
// k3: passC — degrees of R nodes (probe SHARED copy of R hash)
__global__ __launch_bounds__(PTPB) void k3_passC(
        const long long* __restrict__ ei64, const float* __restrict__ ew, int E) {
    __shared__ int rt[RTBL];                         // 16 KB
    {
        const int4* src = (const int4*)g_rtab;
        int4* dst = (int4*)rt;
        for (int i = threadIdx.x; i < RTBL / 4; i += PTPB) dst[i] = src[i];
    }
    __syncthreads();
    const int* ei32 = (const int*)ei64;
    int is32 = g_is32;
    int gsz  = gridDim.x * blockDim.x;
    int gtid = blockIdx.x * blockDim.x + threadIdx.x;
#define DO_C(cc, ee) do {                                                    \
        int _c = (cc);                                                       \
        unsigned _ix = hsh(_c) & RMASK;                                      \
        for (int _p = 0; _p < RTBL; _p++) {                                  \
            int _v = rt[_ix];                                                \
            if (_v == 0) break;                                              \
            if (_v == _c + 1) { atomicAdd(&g_deg[_c], ew[(ee)]); break; }    \
            _ix = (_ix + 1) & RMASK;                                         \
        }                                                                    \
    } while (0)
    if (is32 && ((E & 3) == 0)) {
        const int4* col4 = (const int4*)(ei32 + E);
        int nvec = E >> 2;
        for (int v = gtid; v < nvec; v += gsz) {
            int4 c4 = col4[v]; int e = v * 4;
            DO_C(c4.x, e); DO_C(c4.y, e + 1); DO_C(c4.z, e + 2); DO_C(c4.w, e + 3);
        }
    } else if (!is32 && ((E & 1) == 0)) {
        const longlong2* col2 = (const longlong2*)(ei64 + E);
        int nvec = E >> 1;
        for (int v = gtid; v < nvec; v += gsz) {
            longlong2 c2 = col2[v]; int e = v * 2;
            DO_C((int)c2.x, e); DO_C((int)c2.y, e + 1);
        }
    } else {
        for (int e = gtid; e < E; e += gsz)
            DO_C(is32 ? ei32[E + e] : (int)ei64[E + e], e);
    }
#undef DO_C
}

// ===========================================================================
// k4: tail — layer1 (32 blocks) -> layer2 (8) -> GEMV1 (8) -> GEMV2 (1)
#define TTPB  512
#define MAXM  512
__global__ __launch_bounds__(TTPB) void k4_tail(
    const float* __restrict__ x,
    const long long* __restrict__ wt_idx,
    const long long* __restrict__ mut_idx,
    const float* __restrict__ W1, const float* __restrict__ b1,
    const float* __restrict__ W2, const float* __restrict__ b2,
    const float* __restrict__ aa_emb, const float* __restrict__ pos_emb,
    const float* __restrict__ Wh1, const float* __restrict__ bh1,
    const float* __restrict__ Wh2, const float* __restrict__ bh2,
    const float* __restrict__ Wh3, const float* __restrict__ bh3,
    float* __restrict__ out, int max_pos)
{
    __shared__ float sbuf[1024];
    __shared__ int   mlist[MAXM];
    __shared__ int   mcount;
    const int tid = threadIdx.x;
    const int bid = blockIdx.x;
    unsigned mp0 = g_mph[0], mp1 = g_mph[1], mp2 = g_mph[2];

#define MARRIVE(id, total, mpv) do {                                         \
        __syncthreads();                                                     \
        if (tid == 0) {                                                      \
            __threadfence();                                                 \
            if (atomicAdd(&g_marr[id], 1) == (total) - 1) {                  \
                g_marr[id] = 0; __threadfence(); g_mph[id] = (mpv) + 1u;     \
            }                                                                \
        }                                                                    \
    } while (0)
#define MWAIT(id, mpv) do {                                                  \
        if (tid == 0) { while (g_mph[id] == (mpv)) { } __threadfence(); }    \
        __syncthreads();                                                     \
    } while (0)

    // ---- layer 1 (blocks 0..31): parallel match scan + reg accumulate ----
    {
        float* acc = sbuf;
        int ns1 = min(g_s1_count, MAX_S1);
        int nl1 = min(g_l1e_count, MAX_L1E);
        for (int s = bid; s < ns1; s += 32) {
            int node = g_s1_node[s];
            if (node < 0) continue;
            float degc = g_deg[node] + 1.0f;
            float dc = rsqrtf(degc);
            if (tid == 0) mcount = 0;
            __syncthreads();
            for (int e = tid; e < nl1; e += TTPB) {
                if (g_l1_cslot[e] == s) {
                    int p = atomicAdd(&mcount, 1);
                    if (p < MAXM) mlist[p] = e;
                }
            }
            __syncthreads();
            int mc = min(mcount, MAXM);
            float a = 0.0f;
            if (tid < 128) a = x[(size_t)node * 128 + tid] / degc;
            for (int m = 0; m < mc; m++) {
                int e = mlist[m];
                int r = g_l1_row[e];
                float norm = g_l1_w[e] * rsqrtf(g_deg[r] + 1.0f) * dc;
                if (tid < 128) a += norm * x[(size_t)r * 128 + tid];
            }
            if (tid < 128) acc[tid] = a;
            __syncthreads();
            if (tid < 256) {
                float aj = b1[tid];
#pragma unroll 8
                for (int k = 0; k < 128; k++) aj += acc[k] * W1[k * 256 + tid];
                g_h1[s * 256 + tid] = fmaxf(aj, 0.0f);
            }
            __syncthreads();
        }
    }
    MARRIVE(0, 32, mp0);
    if (bid >= 8) {
        // blocks 8..31: reset hash tables (unused by later tail phases)
        int base = (bid - 8) * TTPB + tid;
        int stride = 24 * TTPB;
        for (int i = base; i < H1TBL; i += stride) g_h1pack[i] = 0;
        for (int i = base; i < RTBL;  i += stride) g_rtab[i]  = 0;
        return;
    }

    // ---- layer 2 (blocks 0..7, 32 outputs each) ----
    MWAIT(0, mp0);
    {
        float* agg   = sbuf;           // 256
        float* spart = sbuf + 256;     // 256
        int ns2 = min(g_s2_count, MAX_S2);
        int nl2 = min(g_l2e_count, MAX_L2E);
        int j0 = bid * 32;
        float zacc = 0.0f;
        for (int s = 0; s < ns2; s++) {
            int cnode = g_s2_node[s];
            float degc = g_deg[cnode] + 1.0f;
            float dc = rsqrtf(degc);
            if (tid < 256) {
                int cs1 = g_s2_s1slot[s];
                float a = (cs1 >= 0) ? g_h1[cs1 * 256 + tid] / degc : 0.0f;
                for (int e = 0; e < nl2; e++) {
                    if (g_l2_cslot[e] == s) {
                        int rslot = g_l2_rslot[e];
                        if (rslot >= 0) {
                            int rnode = g_l2_row[e];
                            float norm = g_l2_w[e] * rsqrtf(g_deg[rnode] + 1.0f) * dc;
                            a += norm * g_h1[rslot * 256 + tid];
                        }
                    }
                }
                agg[tid] = a;
            }
            __syncthreads();
            if (tid < 256) {
                int kc = tid >> 5, j = tid & 31;
                float p = 0.0f;
#pragma unroll 8
                for (int k = kc * 32; k < kc * 32 + 32; k++)
                    p += agg[k] * W2[k * 256 + j0 + j];
                spart[tid] = p;
            }
            __syncthreads();
            if (tid < 32) {
                float sum = b2[j0 + tid];
#pragma unroll
                for (int c = 0; c < 8; c++) sum += spart[c * 32 + tid];
                zacc += g_s2_val[s] * fmaxf(sum, 0.0f);
            }
            __syncthreads();
        }
        if (tid < 32) g_z[j0 + tid] = zacc;
    }
    MARRIVE(1, 8, mp1);

    // ---- head GEMV1 480->512 (blocks 0..7, 64 outputs each) ----
    MWAIT(1, mp1);
    {
        float* feat  = sbuf;           // 480
        float* spart = sbuf + 480;     // 512
        int is32 = g_is32;
        int wtI  = is32 ? ((const int*)wt_idx)[0]  : (int)wt_idx[0];
        int mutI = is32 ? ((const int*)mut_idx)[0] : (int)mut_idx[0];
        if (tid < 256) feat[tid] = g_z[tid];
        else if (tid < 480) {
            int j = tid - 256;
            float v;
            if (j < 64)       v = aa_emb[wtI  * 64 + j];
            else if (j < 128) v = aa_emb[mutI * 64 + (j - 64)];
            else if (j < 192) v = aa_emb[mutI * 64 + (j - 128)] -
                                  aa_emb[wtI  * 64 + (j - 128)];
            else {
                unsigned int low = (unsigned int)(g_argmax_key & 0xFFFFFFFFull);
                int pos = (int)(0xFFFFFFFFu - low);
                if (pos < 0) pos = 0;
                if (pos > max_pos - 1) pos = max_pos - 1;
                v = pos_emb[pos * 32 + (j - 192)];
            }
            feat[tid] = v;
        }
        __syncthreads();
        int kc = tid >> 6, jj = tid & 63;
        int j  = bid * 64 + jj;
        float p = 0.0f;
#pragma unroll 10
        for (int k = kc * 60; k < kc * 60 + 60; k++)
            p += feat[k] * Wh1[k * 512 + j];
        spart[tid] = p;
        __syncthreads();
        if (tid < 64) {
            float sum = bh1[bid * 64 + tid];
#pragma unroll
            for (int c = 0; c < 8; c++) sum += spart[c * 64 + tid];
            g_f1[bid * 64 + tid] = fmaxf(sum, 0.0f);
        }
    }
    MARRIVE(2, 8, mp2);

    if (bid == 1) {
        MWAIT(2, mp2);
        if (tid == 0) {
            g_s2_count = 0; g_l2e_count = 0; g_l1e_count = 0;
            g_s1_count = 0; g_r_count = 0; g_is32 = 0;
            g_argmax_key = 0ull;
        }
        return;
    }
    if (bid != 0) return;

    // ---- head GEMV2 + final dot (block 0) ----
    MWAIT(2, mp2);
    {
        float* sf1   = sbuf;           // 512
        float* spart = sbuf + 512;     // 512
        sf1[tid] = g_f1[tid];
        __syncthreads();
        int kc = tid >> 7, j = tid & 127;
        float p = 0.0f;
#pragma unroll 8
        for (int k = kc * 128; k < kc * 128 + 128; k++)
            p += sf1[k] * Wh2[k * 128 + j];
        spart[kc * 128 + j] = p;
        __syncthreads();
        float* f2 = spart;
        if (tid < 128) {
            float sum = bh2[tid] + spart[tid] + spart[128 + tid] +
                        spart[256 + tid] + spart[384 + tid];
            f2[tid] = fmaxf(sum, 0.0f) * Wh3[tid];
        }
        __syncthreads();
        if (tid < 64) f2[tid] += f2[tid + 64];
        __syncthreads();
        if (tid < 32) {
            float v = f2[tid] + f2[tid + 32];
            for (int o = 16; o > 0; o >>= 1) v += __shfl_down_sync(0xFFFFFFFFu, v, o);
            if (tid == 0) out[0] = v + bh3[0];
        }
    }
#undef MARRIVE
#undef MWAIT
}

// ---------------------------------------------------------------------------
extern "C" void kernel_launch(void* const* d_in, const int* in_sizes, int n_in,
                              void* d_out, int out_size) {
    const float*     x       = (const float*)d_in[0];
    const long long* ei      = (const long long*)d_in[1];
    const float*     ew      = (const float*)d_in[2];
    const float*     mask    = (const float*)d_in[3];
    const long long* wt_idx  = (const long long*)d_in[4];
    const long long* mut_idx = (const long long*)d_in[5];
    const float*     W1      = (const float*)d_in[6];
    const float*     b1      = (const float*)d_in[7];
    const float*     W2      = (const float*)d_in[8];
    const float*     b2      = (const float*)d_in[9];
    const float*     aa_emb  = (const float*)d_in[10];
    const float*     pos_emb = (const float*)d_in[11];
    const float*     Wh1     = (const float*)d_in[12];
    const float*     bh1     = (const float*)d_in[13];
    const float*     Wh2     = (const float*)d_in[14];
    const float*     bh2     = (const float*)d_in[15];
    const float*     Wh3     = (const float*)d_in[16];
    const float*     bh3     = (const float*)d_in[17];
    float*           out     = (float*)d_out;

    int n       = in_sizes[3];
    int E       = in_sizes[2];
    int max_pos = in_sizes[11] / 32;

    k0_mask <<<(n + 255) / 256, 256>>>(mask, ei, n, E);
    k1_passA<<<GRIDP, PTPB>>>(ei, ew, E);
    k2_passB<<<GRIDP, PTPB>>>(ei, ew, E);
    k3_passC<<<GRIDP, PTPB>>>(ei, ew, E);
    k4_tail <<<32, TTPB>>>(x, wt_idx, mut_idx, W1, b1, W2, b2,
                           aa_emb, pos_emb, Wh1, bh1, Wh2, bh2, Wh3, bh3,
                           out, max_pos);
}

// round 9
// speedup vs baseline: 1.1470x; 1.1470x over previous
#include <cuda_runtime.h>
#include <cuda_bf16.h>

// ---------------------------------------------------------------------------
// HGNN, 5-kernel pipeline v4: pass kernels scan edges against a 12.5KB
// shared-memory node BITMAP (word==0 fast path ~4 instr/edge); rare hits
// fall to slow handlers. Passes were measured issue-bound at ~7 instr/edge.
// ---------------------------------------------------------------------------

#define NMAX     100000
#define BMWORDS  3136                    // ceil(100000/32), padded to /4
#define MAX_S2   32
#define MAX_L2E  2048
#define MAX_S1   (MAX_L2E + MAX_S2 + 64)
#define H1TBL    4096
#define H1MASK   4095
#define RTBL     4096
#define RMASK    4095
#define RCAP     3500
#define MAX_L1E  32768
#define GRIDP    296
#define PTPB     1024

__device__ float    g_deg[NMAX];
__device__ int      g_h1pack[H1TBL];     // (slot<<17)|(node+1); 0 empty
__device__ int      g_rtab[RTBL];        // node+1; 0 empty
__device__ unsigned g_bmS2[BMWORDS];     // S2 membership bits
__device__ unsigned g_bmS1[BMWORDS];     // S1 membership bits
__device__ unsigned g_bmR[BMWORDS];      // R membership bits
__device__ int      g_s2_node[MAX_S2];
__device__ float    g_s2_val[MAX_S2];
__device__ int      g_s2_s1slot[MAX_S2];
__device__ int      g_l2_row[MAX_L2E];
__device__ int      g_l2_cslot[MAX_L2E];
__device__ int      g_l2_rslot[MAX_L2E];
__device__ float    g_l2_w[MAX_L2E];
__device__ int      g_s1_node[MAX_S1];   // -1 = wasted slot
__device__ int      g_l1_row[MAX_L1E];
__device__ int      g_l1_cslot[MAX_L1E];
__device__ float    g_l1_w[MAX_L1E];
__device__ float    g_h1[MAX_S1 * 256];
__device__ float    g_z[256];
__device__ float    g_f1[512];
__device__ int      g_s2_count, g_l2e_count, g_l1e_count, g_s1_count, g_r_count, g_is32;
__device__ unsigned long long g_argmax_key;
__device__ int               g_marr[3];
__device__ volatile unsigned g_mph[3];   // monotonic mini phases

__device__ __forceinline__ unsigned hsh(int v) {
    return ((unsigned)v * 2654435761u) >> 13;
}

__device__ void rtab_insert(int node) {
    if (g_r_count >= RCAP) return;
    unsigned idx = hsh(node) & RMASK;
    for (int p = 0; p < RTBL; p++) {
        int cur = atomicCAS(&g_rtab[idx], 0, node + 1);
        if (cur == 0) {
            g_deg[node] = 0.0f;
            atomicOr(&g_bmR[node >> 5], 1u << (node & 31));
            atomicAdd(&g_r_count, 1);
            return;
        }
        if (cur == node + 1) return;
        idx = (idx + 1) & RMASK;
    }
}

// Insert node into S1 hash; returns dense slot; sets S1 bitmap + R set.
__device__ int h1_insert(int node) {
    unsigned idx = hsh(node) & H1MASK;
    int myslot = -1;
    for (int p = 0; p < H1TBL; p++) {
        int v = g_h1pack[idx];
        if (v != 0) {
            if ((v & 0x1FFFF) == node + 1) {
                if (myslot >= 0) g_s1_node[myslot] = -1;
                return v >> 17;
            }
        } else {
            if (myslot < 0) {
                myslot = atomicAdd(&g_s1_count, 1);
                if (myslot >= MAX_S1) return -1;
            }
            int cur = atomicCAS(&g_h1pack[idx], 0, (myslot << 17) | (node + 1));
            if (cur == 0) {
                g_s1_node[myslot] = node;
                atomicOr(&g_bmS1[node >> 5], 1u << (node & 31));
                rtab_insert(node);
                return myslot;
            }
            if ((cur & 0x1FFFF) == node + 1) {
                g_s1_node[myslot] = -1;
                return cur >> 17;
            }
        }
        idx = (idx + 1) & H1MASK;
    }
    return -1;
}

// ===========================================================================
// k0: dtype detect + mask scan (S2 list + S2 bitmap + argmax)
__global__ void k0_mask(const float* __restrict__ mask,
                        const long long* __restrict__ ei64, int n, int E) {
    __shared__ unsigned long long sk[256];
    int i = blockIdx.x * blockDim.x + threadIdx.x;
    int lim = E < 1024 ? E : 1024;
    if (i < lim) {
        long long v = ei64[i];
        bool bad = (v < 0 || v >= (long long)n);
        if (__any_sync(__activemask(), bad)) {
            if ((threadIdx.x & 31) == 0) g_is32 = 1;
        }
    }
    unsigned long long key = 0ull;
    if (i < n) {
        float m = mask[i];
        if (m != 0.0f) {
            int slot = atomicAdd(&g_s2_count, 1);
            if (slot < MAX_S2) {
                g_s2_node[slot] = i; g_s2_val[slot] = m;
                g_s2_s1slot[slot] = h1_insert(i);
                atomicOr(&g_bmS2[i >> 5], 1u << (i & 31));
            }
        }
        unsigned int b  = __float_as_uint(m);
        unsigned int ub = (b & 0x80000000u) ? ~b : (b | 0x80000000u);
        key = (((unsigned long long)ub) << 32) |
              (unsigned long long)(0xFFFFFFFFu - (unsigned)i);
    }
    sk[threadIdx.x] = key;
    __syncthreads();
    for (int o = 128; o > 0; o >>= 1) {
        if (threadIdx.x < o) {
            unsigned long long a = sk[threadIdx.x], b2 = sk[threadIdx.x + o];
            sk[threadIdx.x] = (a > b2) ? a : b2;
        }
        __syncthreads();
    }
    if (threadIdx.x == 0 && sk[0] != 0ull) atomicMax(&g_argmax_key, sk[0]);
}

// --- shared bitmap copy helper (3136 words = 784 int4) ---------------------
#define LOAD_BM(gbm, sbm) do {                                               \
        const int4* _s = (const int4*)(gbm);                                 \
        int4* _d = (int4*)(sbm);                                             \
        for (int _i = threadIdx.x; _i < BMWORDS / 4; _i += PTPB)             \
            _d[_i] = _s[_i];                                                 \
    } while (0)

// ===========================================================================
// k1: passA — bitmap scan vs S2; hits: record L2 edge + S1 hash insert
__global__ __launch_bounds__(PTPB) void k1_passA(
        const long long* __restrict__ ei64, const float* __restrict__ ew, int E) {
    __shared__ unsigned bm[BMWORDS];
    __shared__ int s2n[MAX_S2];
    __shared__ int ns2_s, is32_s;
    LOAD_BM(g_bmS2, bm);
    if (threadIdx.x == 0) { ns2_s = min(g_s2_count, MAX_S2); is32_s = g_is32; }
    __syncthreads();
    int ns2 = ns2_s, is32 = is32_s;
    if (threadIdx.x < ns2) s2n[threadIdx.x] = g_s2_node[threadIdx.x];
    __syncthreads();
    const int* ei32 = (const int*)ei64;
    int gsz  = gridDim.x * blockDim.x;
    int gtid = blockIdx.x * blockDim.x + threadIdx.x;
#define DO_A(cc, ee) do {                                                    \
        int _c = (cc);                                                       \
        unsigned _w = bm[_c >> 5];                                           \
        if (_w != 0u && ((_w >> (_c & 31)) & 1u)) {                          \
            int _ms = -1;                                                    \
            for (int _j = 0; _j < ns2; _j++) if (_c == s2n[_j]) _ms = _j;    \
            if (_ms >= 0) {                                                  \
                int _e = (ee);                                               \
                int _r = is32 ? ei32[_e] : (int)ei64[_e];                    \
                int _sl = atomicAdd(&g_l2e_count, 1);                        \
                if (_sl < MAX_L2E) {                                         \
                    g_l2_row[_sl] = _r; g_l2_cslot[_sl] = _ms;               \
                    g_l2_w[_sl] = ew[_e];                                    \
                    g_l2_rslot[_sl] = h1_insert(_r);                         \
                }                                                            \
            }                                                                \
        }                                                                    \
    } while (0)
    if (is32 && ((E & 3) == 0)) {
        const int4* col4 = (const int4*)(ei32 + E);
        int nvec = E >> 2;
        for (int v = gtid; v < nvec; v += gsz) {
            int4 c4 = col4[v];
            DO_A(c4.x, v * 4); DO_A(c4.y, v * 4 + 1);
            DO_A(c4.z, v * 4 + 2); DO_A(c4.w, v * 4 + 3);
        }
    } else if (!is32 && ((E & 1) == 0)) {
        const longlong2* col2 = (const longlong2*)(ei64 + E);
        int nvec = E >> 1;
        for (int v = gtid; v < nvec; v += gsz) {
            longlong2 c2 = col2[v];
            DO_A((int)c2.x, v * 2); DO_A((int)c2.y, v * 2 + 1);
        }
    } else {
        for (int e = gtid; e < E; e += gsz)
            DO_A(is32 ? ei32[E + e] : (int)ei64[E + e], e);
    }
#undef DO_A
}

// ===========================================================================
// k2: passB — bitmap scan vs S1; hits: global hash probe -> record L1 edge
__global__ __launch_bounds__(PTPB) void k2_passB(
        const long long* __restrict__ ei64, const float* __restrict__ ew, int E) {
    __shared__ unsigned bm[BMWORDS];
    LOAD_BM(g_bmS1, bm);
    __syncthreads();
    const int* ei32 = (const int*)ei64;
    int is32 = g_is32;
    int gsz  = gridDim.x * blockDim.x;
    int gtid = blockIdx.x * blockDim.x + threadIdx.x;
#define DO_B(cc, ee) do {                                                    \
        int _c = (cc);                                                       \
        unsigned _w = bm[_c >> 5];                                           \
        if (_w != 0u && ((_w >> (_c & 31)) & 1u)) {                          \
            unsigned _ix = hsh(_c) & H1MASK; int _sl = -1;                   \
            for (int _p = 0; _p < H1TBL; _p++) {                             \
                int _v = __ldg(&g_h1pack[_ix]);                              \
                if (_v == 0) break;                                          \
                if ((_v & 0x1FFFF) == _c + 1) { _sl = _v >> 17; break; }     \
                _ix = (_ix + 1) & H1MASK;                                    \
            }                                                                \
            if (_sl >= 0) {                                                  \
                int _e = (ee);                                               \
                int _r = is32 ? ei32[_e] : (int)ei64[_e];                    \
                int _ps = atomicAdd(&g_l1e_count, 1);                        \
                if (_ps < MAX_L1E) {                                         \
                    g_l1_row[_ps] = _r; g_l1_cslot[_ps] = _sl;               \
                    g_l1_w[_ps] = ew[_e];                                    \
                    rtab_insert(_r);                                         \
                }                                                            \
            }                                                                \
        }                                                                    \
    } while (0)
    if (is32 && ((E & 3) == 0)) {
        const int4* col4 = (const int4*)(ei32 + E);
        int nvec = E >> 2;
        for (int v = gtid; v < nvec; v += gsz) {
            int4 c4 = col4[v];
            DO_B(c4.x, v * 4); DO_B(c4.y, v * 4 + 1);
            DO_B(c4.z, v * 4 + 2); DO_B(c4.w, v * 4 + 3);
        }
    } else if (!is32 && ((E & 1) == 0)) {
        const longlong2* col2 = (const longlong2*)(ei64 + E);
        int nvec = E >> 1;
        for (int v = gtid; v < nvec; v += gsz) {
            longlong2 c2 = col2[v];
            DO_B((int)c2.x, v * 2); DO_B((int)c2.y, v * 2 + 1);
        }
    } else {
        for (int e = gtid; e < E; e += gsz)
            DO_B(is32 ? ei32[E + e] : (int)ei64[E + e], e);
    }
#undef DO_B
}

// ===========================================================================
// k3: passC — bitmap scan vs R; hits: accumulate degree
__global__ __launch_bounds__(PTPB) void k3_passC(
        const long long* __restrict__ ei64, const float* __restrict__ ew, int E) {
    __shared__ unsigned bm[BMWORDS];
    LOAD_BM(g_bmR, bm);
    __syncthreads();
    const int* ei32 = (const int*)ei64;
    int is32 = g_is32;
    int gsz  = gridDim.x * blockDim.x;
    int gtid = blockIdx.x * blockDim.x + threadIdx.x;
#define DO_C(cc, ee) do {                                                    \
        int _c = (cc);                                                       \
        unsigned _w = bm[_c >> 5];                                           \
        if (_w != 0u && ((_w >> (_c & 31)) & 1u))                            \
            atomicAdd(&g_deg[_c], ew[(ee)]);                                 \
    } while (0)
    if (is32 && ((E & 3) == 0)) {
        const int4* col4 = (const int4*)(ei32 + E);
        int nvec = E >> 2;
        for (int v = gtid; v < nvec; v += gsz) {
            int4 c4 = col4[v];
            DO_C(c4.x, v * 4); DO_C(c4.y, v * 4 + 1);
            DO_C(c4.z, v * 4 + 2); DO_C(c4.w, v * 4 + 3);
        }
    } else if (!is32 && ((E & 1) == 0)) {
        const longlong2* col2 = (const longlong2*)(ei64 + E);
        int nvec = E >> 1;
        for (int v = gtid; v < nvec; v += gsz) {
            longlong2 c2 = col2[v];
            DO_C((int)c2.x, v * 2); DO_C((int)c2.y, v * 2 + 1);
        }
    } else {
        for (int e = gtid; e < E; e += gsz)
            DO_C(is32 ? ei32[E + e] : (int)ei64[E + e], e);
    }
#undef DO_C
}

// ===========================================================================
// k4: tail — layer1 (32 blocks) -> layer2 (8) -> GEMV1 (8) -> GEMV2 (1)
#define TTPB  512
#define MAXM  512
__global__ __launch_bounds__(TTPB) void k4_tail(
    const float* __restrict__ x,
    const long long* __restrict__ wt_idx,
    const long long* __restrict__ mut_idx,
    const float* __restrict__ W1, const float* __restrict__ b1,
    const float* __restrict__ W2, const float* __restrict__ b2,
    const float* __restrict__ aa_emb, const float* __restrict__ pos_emb,
    const float* __restrict__ Wh1, const float* __restrict__ bh1,
    const float* __restrict__ Wh2, const float* __restrict__ bh2,
    const float* __restrict__ Wh3, const float* __restrict__ bh3,
    float* __restrict__ out, int max_pos)
{
    __shared__ float sbuf[1024];
    __shared__ int   mlist[MAXM];
    __shared__ int   mcount;
    const int tid = threadIdx.x;
    const int bid = blockIdx.x;
    unsigned mp0 = g_mph[0], mp1 = g_mph[1], mp2 = g_mph[2];

#define MARRIVE(id, total, mpv) do {                                         \
        __syncthreads();                                                     \
        if (tid == 0) {                                                      \
            __threadfence();                                                 \
            if (atomicAdd(&g_marr[id], 1) == (total) - 1) {                  \
                g_marr[id] = 0; __threadfence(); g_mph[id] = (mpv) + 1u;     \
            }                                                                \
        }                                                                    \
    } while (0)
#define MWAIT(id, mpv) do {                                                  \
        if (tid == 0) { while (g_mph[id] == (mpv)) { } __threadfence(); }    \
        __syncthreads();                                                     \
    } while (0)

    // ---- layer 1 (blocks 0..31): match scan + unrolled accumulate --------
    {
        float* acc = sbuf;
        int ns1 = min(g_s1_count, MAX_S1);
        int nl1 = min(g_l1e_count, MAX_L1E);
        for (int s = bid; s < ns1; s += 32) {
            int node = g_s1_node[s];
            if (node < 0) continue;
            float degc = g_deg[node] + 1.0f;
            float dc = rsqrtf(degc);
            if (tid == 0) mcount = 0;
            __syncthreads();
            for (int e = tid; e < nl1; e += TTPB) {
                if (g_l1_cslot[e] == s) {
                    int p = atomicAdd(&mcount, 1);
                    if (p < MAXM) mlist[p] = e;
                }
            }
            __syncthreads();
            int mc = min(mcount, MAXM);
            float a = 0.0f;
            if (tid < 128) a = x[(size_t)node * 128 + tid] / degc;
            int m = 0;
            for (; m + 3 < mc; m += 4) {               // MLP-4 unroll
                int e0 = mlist[m],     e1 = mlist[m + 1];
                int e2 = mlist[m + 2], e3 = mlist[m + 3];
                int r0 = g_l1_row[e0], r1 = g_l1_row[e1];
                int r2 = g_l1_row[e2], r3 = g_l1_row[e3];
                float n0 = g_l1_w[e0] * rsqrtf(g_deg[r0] + 1.0f) * dc;
                float n1 = g_l1_w[e1] * rsqrtf(g_deg[r1] + 1.0f) * dc;
                float n2 = g_l1_w[e2] * rsqrtf(g_deg[r2] + 1.0f) * dc;
                float n3 = g_l1_w[e3] * rsqrtf(g_deg[r3] + 1.0f) * dc;
                if (tid < 128) {
                    float v0 = x[(size_t)r0 * 128 + tid];
                    float v1 = x[(size_t)r1 * 128 + tid];
                    float v2 = x[(size_t)r2 * 128 + tid];
                    float v3 = x[(size_t)r3 * 128 + tid];
                    a += n0 * v0 + n1 * v1 + n2 * v2 + n3 * v3;
                }
            }
            for (; m < mc; m++) {
                int e = mlist[m];
                int r = g_l1_row[e];
                float norm = g_l1_w[e] * rsqrtf(g_deg[r] + 1.0f) * dc;
                if (tid < 128) a += norm * x[(size_t)r * 128 + tid];
            }
            if (tid < 128) acc[tid] = a;
            __syncthreads();
            if (tid < 256) {
                float aj = b1[tid];
#pragma unroll 8
                for (int k = 0; k < 128; k++) aj += acc[k] * W1[k * 256 + tid];
                g_h1[s * 256 + tid] = fmaxf(aj, 0.0f);
            }
            __syncthreads();
        }
    }
    MARRIVE(0, 32, mp0);
    if (bid >= 8) {
        // blocks 8..31: reset hash tables + bitmaps (unused later in tail)
        int base = (bid - 8) * TTPB + tid;
        int stride = 24 * TTPB;
        for (int i = base; i < H1TBL; i += stride) g_h1pack[i] = 0;
        for (int i = base; i < RTBL;  i += stride) g_rtab[i]  = 0;
        for (int i = base; i < BMWORDS; i += stride) {
            g_bmS2[i] = 0u; g_bmS1[i] = 0u; g_bmR[i] = 0u;
        }
        return;
    }

    // ---- layer 2 (blocks 0..7, 32 outputs each) ----
    MWAIT(0, mp0);
    {
        float* agg   = sbuf;           // 256
        float* spart = sbuf + 256;     // 256
        int ns2 = min(g_s2_count, MAX_S2);
        int nl2 = min(g_l2e_count, MAX_L2E);
        int j0 = bid * 32;
        float zacc = 0.0f;
        for (int s = 0; s < ns2; s++) {
            int cnode = g_s2_node[s];
            float degc = g_deg[cnode] + 1.0f;
            float dc = rsqrtf(degc);
            if (tid < 256) {
                int cs1 = g_s2_s1slot[s];
                float a = (cs1 >= 0) ? g_h1[cs1 * 256 + tid] / degc : 0.0f;
                for (int e = 0; e < nl2; e++) {
                    if (g_l2_cslot[e] == s) {
                        int rslot = g_l2_rslot[e];
                        if (rslot >= 0) {
                            int rnode = g_l2_row[e];
                            float norm = g_l2_w[e] * rsqrtf(g_deg[rnode] + 1.0f) * dc;
                            a += norm * g_h1[rslot * 256 + tid];
                        }
                    }
                }
                agg[tid] = a;
            }
            __syncthreads();
            if (tid < 256) {
                int kc = tid >> 5, j = tid & 31;
                float p = 0.0f;
#pragma unroll 8
                for (int k = kc * 32; k < kc * 32 + 32; k++)
                    p += agg[k] * W2[k * 256 + j0 + j];
                spart[tid] = p;
            }
            __syncthreads();
            if (tid < 32) {
                float sum = b2[j0 + tid];
#pragma unroll
                for (int c = 0; c < 8; c++) sum += spart[c * 32 + tid];
                zacc += g_s2_val[s] * fmaxf(sum, 0.0f);
            }
            __syncthreads();
        }
        if (tid < 32) g_z[j0 + tid] = zacc;
    }
    MARRIVE(1, 8, mp1);

    // ---- head GEMV1 480->512 (blocks 0..7, 64 outputs each) ----
    MWAIT(1, mp1);
    {
        float* feat  = sbuf;           // 480
        float* spart = sbuf + 480;     // 512
        int is32 = g_is32;
        int wtI  = is32 ? ((const int*)wt_idx)[0]  : (int)wt_idx[0];
        int mutI = is32 ? ((const int*)mut_idx)[0] : (int)mut_idx[0];
        if (tid < 256) feat[tid] = g_z[tid];
        else if (tid < 480) {
            int j = tid - 256;
            float v;
            if (j < 64)       v = aa_emb[wtI  * 64 + j];
            else if (j < 128) v = aa_emb[mutI * 64 + (j - 64)];
            else if (j < 192) v = aa_emb[mutI * 64 + (j - 128)] -
                                  aa_emb[wtI  * 64 + (j - 128)];
            else {
                unsigned int low = (unsigned int)(g_argmax_key & 0xFFFFFFFFull);
                int pos = (int)(0xFFFFFFFFu - low);
                if (pos < 0) pos = 0;
                if (pos > max_pos - 1) pos = max_pos - 1;
                v = pos_emb[pos * 32 + (j - 192)];
            }
            feat[tid] = v;
        }
        __syncthreads();
        int kc = tid >> 6, jj = tid & 63;
        int j  = bid * 64 + jj;
        float p = 0.0f;
#pragma unroll 10
        for (int k = kc * 60; k < kc * 60 + 60; k++)
            p += feat[k] * Wh1[k * 512 + j];
        spart[tid] = p;
        __syncthreads();
        if (tid < 64) {
            float sum = bh1[bid * 64 + tid];
#pragma unroll
            for (int c = 0; c < 8; c++) sum += spart[c * 64 + tid];
            g_f1[bid * 64 + tid] = fmaxf(sum, 0.0f);
        }
    }
    MARRIVE(2, 8, mp2);

    if (bid == 1) {
        MWAIT(2, mp2);
        if (tid == 0) {
            g_s2_count = 0; g_l2e_count = 0; g_l1e_count = 0;
            g_s1_count = 0; g_r_count = 0; g_is32 = 0;
            g_argmax_key = 0ull;
        }
        return;
    }
    if (bid != 0) return;

    // ---- head GEMV2 + final dot (block 0) ----
    MWAIT(2, mp2);
    {
        float* sf1   = sbuf;           // 512
        float* spart = sbuf + 512;     // 512
        sf1[tid] = g_f1[tid];
        __syncthreads();
        int kc = tid >> 7, j = tid & 127;
        float p = 0.0f;
#pragma unroll 8
        for (int k = kc * 128; k < kc * 128 + 128; k++)
            p += sf1[k] * Wh2[k * 128 + j];
        spart[kc * 128 + j] = p;
        __syncthreads();
        float* f2 = spart;
        if (tid < 128) {
            float sum = bh2[tid] + spart[tid] + spart[128 + tid] +
                        spart[256 + tid] + spart[384 + tid];
            f2[tid] = fmaxf(sum, 0.0f) * Wh3[tid];
        }
        __syncthreads();
        if (tid < 64) f2[tid] += f2[tid + 64];
        __syncthreads();
        if (tid < 32) {
            float v = f2[tid] + f2[tid + 32];
            for (int o = 16; o > 0; o >>= 1) v += __shfl_down_sync(0xFFFFFFFFu, v, o);
            if (tid == 0) out[0] = v + bh3[0];
        }
    }
#undef MARRIVE
#undef MWAIT
}

// ---------------------------------------------------------------------------
extern "C" void kernel_launch(void* const* d_in, const int* in_sizes, int n_in,
                              void* d_out, int out_size) {
    const float*     x       = (const float*)d_in[0];
    const long long* ei      = (const long long*)d_in[1];
    const float*     ew      = (const float*)d_in[2];
    const float*     mask    = (const float*)d_in[3];
    const long long* wt_idx  = (const long long*)d_in[4];
    const long long* mut_idx = (const long long*)d_in[5];
    const float*     W1      = (const float*)d_in[6];
    const float*     b1      = (const float*)d_in[7];
    const float*     W2      = (const float*)d_in[8];
    const float*     b2      = (const float*)d_in[9];
    const float*     aa_emb  = (const float*)d_in[10];
    const float*     pos_emb = (const float*)d_in[11];
    const float*     Wh1     = (const float*)d_in[12];
    const float*     bh1     = (const float*)d_in[13];
    const float*     Wh2     = (const float*)d_in[14];
    const float*     bh2     = (const float*)d_in[15];
    const float*     Wh3     = (const float*)d_in[16];
    const float*     bh3     = (const float*)d_in[17];
    float*           out     = (float*)d_out;

    int n       = in_sizes[3];
    int E       = in_sizes[2];
    int max_pos = in_sizes[11] / 32;

    k0_mask <<<(n + 255) / 256, 256>>>(mask, ei, n, E);
    k1_passA<<<GRIDP, PTPB>>>(ei, ew, E);
    k2_passB<<<GRIDP, PTPB>>>(ei, ew, E);
    k3_passC<<<GRIDP, PTPB>>>(ei, ew, E);
    k4_tail <<<32, TTPB>>>(x, wt_idx, mut_idx, W1, b1, W2, b2,
                           aa_emb, pos_emb, Wh1, bh1, Wh2, bh2, Wh3, bh3,
                           out, max_pos);
}